// round 4
// baseline (speedup 1.0000x reference)
#include <cuda_runtime.h>
#include <cuda_bf16.h>
#include <cstdint>
#include <math.h>

// ----------------------------------------------------------------------------
// GroupedSidechannelCrossAttention
//   q = x @ Wq                      (2048 x 2048) * (2048 x 2048)
//   k/v = channel_states @ Wk/Wv    (512 x 2048) * (2048 x 512) each
//   per-token tiny-K attention (K=32 latents, GQA 16 heads / 4 kv groups)
//   out = (y @ Wo) * tanh(gate)
//
// Big GEMMs run on tensor cores in bf16 with the 3-way split trick for fp32-
// class accuracy:  A'' = [A_hi | A_hi | A_lo],  B'' = [B_hi | B_lo | B_hi]
// concatenated along K (K''=6144) -> hi*hi + hi*lo + lo*hi, err ~1e-5.
// ----------------------------------------------------------------------------

#define KK3 6144   // 3 * 2048

// ------------------------- device scratch (static) --------------------------
__device__ __nv_bfloat16 g_xs  [2048u * 6144u]; // x split       [2048][6144]
__device__ __nv_bfloat16 g_Wqs [6144u * 2048u]; // Wq split      [6144][2048]
__device__ __nv_bfloat16 g_css [512u  * 6144u]; // ch.states split [512][6144]
__device__ __nv_bfloat16 g_Wkvs[6144u * 1024u]; // Wk|Wv split   [6144][1024]
__device__ __nv_bfloat16 g_ys  [2048u * 6144u]; // y split       [2048][6144]
__device__ __nv_bfloat16 g_Wos [6144u * 2048u]; // Wo split      [6144][2048]
__device__ float         g_Q   [2048u * 2048u]; // fp32 Q
__device__ float         g_KV  [512u  * 1024u]; // fp32 [k | v] proj

// ----------------------------- helpers --------------------------------------
__device__ __forceinline__ void split2(float v, __nv_bfloat16& hi, __nv_bfloat16& lo) {
    hi = __float2bfloat16(v);
    lo = __float2bfloat16(v - __bfloat162float(hi));
}

__device__ __forceinline__ uint32_t smem_u32(const void* p) {
    return (uint32_t)__cvta_generic_to_shared(p);
}
__device__ __forceinline__ void cp16(uint32_t dst, const void* src) {
    asm volatile("cp.async.cg.shared.global [%0], [%1], 16;\n" :: "r"(dst), "l"(src));
}
__device__ __forceinline__ void cp_commit() { asm volatile("cp.async.commit_group;\n" ::: "memory"); }
__device__ __forceinline__ void cp_wait0()  { asm volatile("cp.async.wait_group 0;\n" ::: "memory"); }
__device__ __forceinline__ void cp_wait1()  { asm volatile("cp.async.wait_group 1;\n" ::: "memory"); }

// --------------------------- split kernels -----------------------------------
// A-side: src [R][2048] fp32 -> dst [R][6144] = [hi | hi | lo]
__global__ void split_A_kernel(const float* __restrict__ src, int which) {
    __nv_bfloat16* dst = (which == 0) ? g_xs : g_css;
    unsigned idx = blockIdx.x * 256u + threadIdx.x;
    unsigned r = idx >> 11;          // /2048
    unsigned k = idx & 2047u;
    float v = src[idx];
    __nv_bfloat16 hi, lo; split2(v, hi, lo);
    size_t rb = (size_t)r * 6144u;
    dst[rb + k]         = hi;
    dst[rb + 2048u + k] = hi;
    dst[rb + 4096u + k] = lo;
}

// B-side: W [2048][N] fp32 -> dst [6144][dstN], cols [colofs, colofs+N) = [hi | lo | hi]
__global__ void split_B_kernel(const float* __restrict__ W, int N, int dstN,
                               int colofs, int which) {
    __nv_bfloat16* dst = (which == 0) ? g_Wqs : (which == 1 ? g_Wkvs : g_Wos);
    unsigned idx = blockIdx.x * 256u + threadIdx.x;
    unsigned k = idx / (unsigned)N;
    unsigned n = idx - k * (unsigned)N;
    float v = W[idx];
    __nv_bfloat16 hi, lo; split2(v, hi, lo);
    size_t col = (size_t)colofs + n;
    dst[(size_t)k            * dstN + col] = hi;
    dst[(size_t)(k + 2048u)  * dstN + col] = lo;
    dst[(size_t)(k + 4096u)  * dstN + col] = hi;
}

// ----------------------------- GEMM kernel -----------------------------------
// C[M][N] (fp32) = A''[M][6144] (bf16) * B''[6144][N] (bf16), fp32 accum.
// Block tile 128x128x32, 8 warps (2x4), warp tile 64x32, mma m16n8k16.
#define GBM 128
#define GBN 128
#define GBK 32
#define ASTR 40    // 32 + 8 pad (bf16)  -> conflict-free
#define BSTR 136   // 128 + 8 pad (bf16) -> conflict-free

__global__ __launch_bounds__(256)
void gemm_bf16_kernel(int which, float* __restrict__ outp,
                      const float* __restrict__ gate, int M, int N) {
    const __nv_bfloat16 *A, *B;
    float* C;
    if      (which == 0) { A = g_xs;  B = g_Wqs;  C = g_Q;  }
    else if (which == 1) { A = g_css; B = g_Wkvs; C = g_KV; }
    else                 { A = g_ys;  B = g_Wos;  C = outp; }

    __shared__ __nv_bfloat16 As[2][GBM][ASTR];
    __shared__ __nv_bfloat16 Bs[2][GBK][BSTR];

    const int t = threadIdx.x;
    const int m_base = blockIdx.y * GBM;
    const int n_base = blockIdx.x * GBN;

    auto load_tiles = [&](int s, int k0) {
        #pragma unroll
        for (int i = 0; i < 2; i++) {               // A: 128 rows x 64B
            int e   = t + i * 256;
            int row = e >> 2;
            int co  = (e & 3) * 8;
            cp16(smem_u32(&As[s][row][co]),
                 A + (size_t)(m_base + row) * KK3 + k0 + co);
        }
        #pragma unroll
        for (int i = 0; i < 2; i++) {               // B: 32 rows x 256B
            int e   = t + i * 256;
            int row = e >> 4;
            int co  = (e & 15) * 8;
            cp16(smem_u32(&Bs[s][row][co]),
                 B + (size_t)(k0 + row) * N + n_base + co);
        }
    };

    const int lane = t & 31;
    const int wid  = t >> 5;
    const int wm = (wid >> 2) * 64;   // warp row offset (2 warps along M)
    const int wn = (wid & 3) * 32;    // warp col offset (4 warps along N)

    float acc[4][4][4];
    #pragma unroll
    for (int i = 0; i < 4; i++)
        #pragma unroll
        for (int j = 0; j < 4; j++)
            #pragma unroll
            for (int r = 0; r < 4; r++) acc[i][j][r] = 0.f;

    load_tiles(0, 0);
    cp_commit();

    const int nk = KK3 / GBK;   // 192
    for (int kt = 0; kt < nk; kt++) {
        int cur = kt & 1;
        if (kt + 1 < nk) { load_tiles(cur ^ 1, (kt + 1) * GBK); cp_commit(); cp_wait1(); }
        else             { cp_wait0(); }
        __syncthreads();

        #pragma unroll
        for (int ks = 0; ks < 2; ks++) {
            int k16 = ks * 16;
            uint32_t a[4][4], bb[4][2];
            int arow = wm + (lane & 15);
            int acol = k16 + (lane >> 4) * 8;
            #pragma unroll
            for (int mi = 0; mi < 4; mi++) {
                uint32_t addr = smem_u32(&As[cur][arow + mi * 16][acol]);
                asm volatile("ldmatrix.sync.aligned.m8n8.x4.shared.b16 {%0,%1,%2,%3}, [%4];\n"
                    : "=r"(a[mi][0]), "=r"(a[mi][1]), "=r"(a[mi][2]), "=r"(a[mi][3])
                    : "r"(addr));
            }
            int brow = k16 + (lane & 15);
            #pragma unroll
            for (int ni = 0; ni < 4; ni++) {
                uint32_t addr = smem_u32(&Bs[cur][brow][wn + ni * 8]);
                asm volatile("ldmatrix.sync.aligned.m8n8.x2.trans.shared.b16 {%0,%1}, [%2];\n"
                    : "=r"(bb[ni][0]), "=r"(bb[ni][1]) : "r"(addr));
            }
            #pragma unroll
            for (int mi = 0; mi < 4; mi++)
                #pragma unroll
                for (int ni = 0; ni < 4; ni++) {
                    asm volatile(
                        "mma.sync.aligned.m16n8k16.row.col.f32.bf16.bf16.f32 "
                        "{%0,%1,%2,%3}, {%4,%5,%6,%7}, {%8,%9}, {%0,%1,%2,%3};\n"
                        : "+f"(acc[mi][ni][0]), "+f"(acc[mi][ni][1]),
                          "+f"(acc[mi][ni][2]), "+f"(acc[mi][ni][3])
                        : "r"(a[mi][0]), "r"(a[mi][1]), "r"(a[mi][2]), "r"(a[mi][3]),
                          "r"(bb[ni][0]), "r"(bb[ni][1]));
                }
        }
        __syncthreads();
    }

    float gs = (which == 2) ? tanhf(gate[0]) : 1.0f;
    const int g  = lane >> 2;
    const int t4 = lane & 3;
    #pragma unroll
    for (int mi = 0; mi < 4; mi++)
        #pragma unroll
        for (int ni = 0; ni < 4; ni++) {
            size_t row0 = (size_t)m_base + wm + mi * 16 + g;
            size_t col  = (size_t)n_base + wn + ni * 8 + t4 * 2;
            C[row0 * N + col]           = acc[mi][ni][0] * gs;
            C[row0 * N + col + 1]       = acc[mi][ni][1] * gs;
            C[(row0 + 8) * N + col]     = acc[mi][ni][2] * gs;
            C[(row0 + 8) * N + col + 1] = acc[mi][ni][3] * gs;
        }
}

// --------------------------- attention kernel --------------------------------
// 1 block per token (B*T = 2048 blocks, 256 threads = 8 warps, 2 heads/warp).
// g_KV row layout: [(b*8+ch)*32 + latent][ k: g*128+d | v: 512 + g*128+d ]
// Writes y directly in split-bf16 layout into g_ys [2048][6144] = [hi|hi|lo].
__global__ __launch_bounds__(256)
void attn_kernel(const int* __restrict__ mask) {
    const int tg = blockIdx.x;          // 0..2047  (= b*1024 + t)
    const int b  = tg >> 10;
    const int ch = mask[tg];
    const size_t kvrow0 = (size_t)((b * 8 + ch) * 32);

    __shared__ float q_s[2048];
    __shared__ float attn_s[8][32];

    {   // stage q row (16 heads x 128) in smem
        const float4* src = (const float4*)(g_Q + (size_t)tg * 2048);
        float4* dst = (float4*)q_s;
        for (int i = threadIdx.x; i < 512; i += 256) dst[i] = src[i];
    }
    __syncthreads();

    const int wid = threadIdx.x >> 5;
    const int lane = threadIdx.x & 31;
    const float scale = 0.08838834764831845f;   // 1/sqrt(128)

    for (int hh = 0; hh < 2; hh++) {
        const int h = wid * 2 + hh;             // head 0..15
        const int g = h >> 2;                   // kv group

        // ---- phase 1: scores (lane = latent), dot over d=128 ----
        const float* krow = g_KV + (kvrow0 + lane) * 1024 + g * 128;
        const float* qh = q_s + h * 128;
        float s = 0.f;
        #pragma unroll 8
        for (int d = 0; d < 128; d += 4) {
            float4 k4 = *(const float4*)(krow + d);
            s += qh[d] * k4.x + qh[d + 1] * k4.y + qh[d + 2] * k4.z + qh[d + 3] * k4.w;
        }
        s *= scale;

        // ---- softmax over 32 latents (warp-wide) ----
        float m = s;
        #pragma unroll
        for (int o = 16; o; o >>= 1) m = fmaxf(m, __shfl_xor_sync(0xffffffffu, m, o));
        float e = __expf(s - m);
        float sum = e;
        #pragma unroll
        for (int o = 16; o; o >>= 1) sum += __shfl_xor_sync(0xffffffffu, sum, o);
        attn_s[wid][lane] = e / sum;
        __syncwarp();

        // ---- phase 2: y[d] (lane covers d = lane*4 .. +3), sum over latents ----
        float4 acc = make_float4(0.f, 0.f, 0.f, 0.f);
        const float* vbase = g_KV + kvrow0 * 1024 + 512 + g * 128 + lane * 4;
        #pragma unroll
        for (int kl = 0; kl < 32; kl++) {
            float w = attn_s[wid][kl];
            float4 v4 = *(const float4*)(vbase + (size_t)kl * 1024);
            acc.x += w * v4.x; acc.y += w * v4.y; acc.z += w * v4.z; acc.w += w * v4.w;
        }

        // ---- write split y: [hi | hi | lo] along the 6144-wide row ----
        float vals[4] = {acc.x, acc.y, acc.z, acc.w};
        __nv_bfloat16 hi[4], lo[4];
        #pragma unroll
        for (int i = 0; i < 4; i++) split2(vals[i], hi[i], lo[i]);
        __nv_bfloat162 hp0 = __halves2bfloat162(hi[0], hi[1]);
        __nv_bfloat162 hp1 = __halves2bfloat162(hi[2], hi[3]);
        __nv_bfloat162 lp0 = __halves2bfloat162(lo[0], lo[1]);
        __nv_bfloat162 lp1 = __halves2bfloat162(lo[2], lo[3]);
        size_t base = (size_t)tg * 6144u + h * 128 + lane * 4;
        *(__nv_bfloat162*)(g_ys + base)              = hp0;
        *(__nv_bfloat162*)(g_ys + base + 2)          = hp1;
        *(__nv_bfloat162*)(g_ys + base + 2048)       = hp0;
        *(__nv_bfloat162*)(g_ys + base + 2048 + 2)   = hp1;
        *(__nv_bfloat162*)(g_ys + base + 4096)       = lp0;
        *(__nv_bfloat162*)(g_ys + base + 4096 + 2)   = lp1;
        __syncwarp();
    }
}

// ------------------------------- launcher ------------------------------------
extern "C" void kernel_launch(void* const* d_in, const int* in_sizes, int n_in,
                              void* d_out, int out_size) {
    const float* x    = (const float*)d_in[0];   // (2,1024,2048)
    const float* cs   = (const float*)d_in[1];   // (2,8,32,2048)
    const int*   mask = (const int*)  d_in[2];   // (2,1024)
    const float* Wq   = (const float*)d_in[3];   // (2048,2048)
    const float* Wk   = (const float*)d_in[4];   // (2048,512)
    const float* Wv   = (const float*)d_in[5];   // (2048,512)
    const float* Wo   = (const float*)d_in[6];   // (2048,2048)
    const float* gate = (const float*)d_in[7];   // (1,)
    float* out = (float*)d_out;

    // 1) splits
    split_A_kernel<<<(2048u * 2048u) / 256u, 256>>>(x, 0);
    split_A_kernel<<<(512u  * 2048u) / 256u, 256>>>(cs, 1);
    split_B_kernel<<<(2048u * 2048u) / 256u, 256>>>(Wq, 2048, 2048, 0,   0);
    split_B_kernel<<<(2048u * 512u)  / 256u, 256>>>(Wk, 512,  1024, 0,   1);
    split_B_kernel<<<(2048u * 512u)  / 256u, 256>>>(Wv, 512,  1024, 512, 1);
    split_B_kernel<<<(2048u * 2048u) / 256u, 256>>>(Wo, 2048, 2048, 0,   2);

    // 2) Q = x @ Wq  (2048 x 2048)
    gemm_bf16_kernel<<<dim3(2048 / GBN, 2048 / GBM), 256>>>(0, nullptr, gate, 2048, 2048);

    // 3) [K|V] = channel_states @ [Wk|Wv]  (512 x 1024)
    gemm_bf16_kernel<<<dim3(1024 / GBN, 512 / GBM), 256>>>(1, nullptr, gate, 512, 1024);

    // 4) attention -> y (split layout)
    attn_kernel<<<2048, 256>>>(mask);

    // 5) out = (y @ Wo) * tanh(gate)
    gemm_bf16_kernel<<<dim3(2048 / GBN, 2048 / GBM), 256>>>(2, out, gate, 2048, 2048);
}

// round 6
// speedup vs baseline: 1.2188x; 1.2188x over previous
#include <cuda_runtime.h>
#include <cuda_bf16.h>
#include <cstdint>
#include <math.h>

// ----------------------------------------------------------------------------
// GroupedSidechannelCrossAttention — optimized mma.sync edition
//   (tcgen05 unavailable: harness PTX targets sm_103, not sm_103a)
//
//   Big GEMMs on legacy tensor cores: mma.sync.m16n8k16 bf16 / fp32-accum,
//   CTA tile 128x256x64, 512 threads (16 warps, 2x8), warp tile 64x32,
//   3-stage cp.async pipeline, padded smem (no swizzle), both operands
//   K-major (weights stored transposed+split), ldmatrix x4 non-trans.
//
//   fp32-class accuracy via 3-way bf16 split along K (K''=6144):
//   A''=[A_hi|A_hi|A_lo], B''=[B_hi|B_lo|B_hi] -> hi*hi + hi*lo + lo*hi.
//
//   KV projection uses split-K=8 (128 CTAs) + tiny reduce kernel.
// ----------------------------------------------------------------------------

#define KK3 6144
#define BM  128
#define BN  256
#define BK  64
#define ASTRIDE 72            // 64 + 8 pad (bf16) -> conflict-free ldmatrix
#define A_BYTES (128 * ASTRIDE * 2)   // 18432
#define B_BYTES (256 * ASTRIDE * 2)   // 36864
#define STAGE_BYTES (A_BYTES + B_BYTES)  // 55296
#define SMEM_DYN (3 * STAGE_BYTES + 256)
#define KV_SPLITS 8
#define KV_NK 12              // 6144 / (8*64)

// ------------------------- device scratch (static) --------------------------
__device__ __nv_bfloat16 g_xs  [2048u * 6144u]; // x split         [2048][6144]
__device__ __nv_bfloat16 g_Wqs [2048u * 6144u]; // Wq^T split      [2048][6144]
__device__ __nv_bfloat16 g_css [512u  * 6144u]; // ch.states split [512][6144]
__device__ __nv_bfloat16 g_Wkvs[1024u * 6144u]; // [Wk|Wv]^T split [1024][6144]
__device__ __nv_bfloat16 g_ys  [2048u * 6144u]; // y split         [2048][6144]
__device__ __nv_bfloat16 g_Wos [2048u * 6144u]; // Wo^T split      [2048][6144]
__device__ float         g_Q   [2048u * 2048u]; // fp32 Q
__device__ float         g_KV  [512u  * 1024u]; // fp32 [k | v]
__device__ float         g_KVp [KV_SPLITS * 512u * 1024u]; // split-K partials

// ----------------------------- helpers --------------------------------------
__device__ __forceinline__ void split2(float v, __nv_bfloat16& hi, __nv_bfloat16& lo) {
    hi = __float2bfloat16(v);
    lo = __float2bfloat16(v - __bfloat162float(hi));
}
__device__ __forceinline__ uint32_t smem_u32(const void* p) {
    return (uint32_t)__cvta_generic_to_shared(p);
}
__device__ __forceinline__ void cp16(uint32_t dst, const void* src) {
    asm volatile("cp.async.cg.shared.global [%0], [%1], 16;\n" :: "r"(dst), "l"(src));
}
__device__ __forceinline__ void cp_commit() { asm volatile("cp.async.commit_group;\n" ::: "memory"); }
__device__ __forceinline__ void cp_wait0()  { asm volatile("cp.async.wait_group 0;\n" ::: "memory"); }
__device__ __forceinline__ void cp_wait1()  { asm volatile("cp.async.wait_group 1;\n" ::: "memory"); }

// --------------------------- split kernels -----------------------------------
// A-side: src [R][2048] fp32 -> dst [R][6144] = [hi | hi | lo]
__global__ void split_A_kernel(const float* __restrict__ src, int which) {
    __nv_bfloat16* dst = (which == 0) ? g_xs : g_css;
    unsigned idx = blockIdx.x * 256u + threadIdx.x;
    unsigned r = idx >> 11;
    unsigned k = idx & 2047u;
    float v = src[idx];
    __nv_bfloat16 hi, lo; split2(v, hi, lo);
    size_t rb = (size_t)r * 6144u;
    dst[rb + k]         = hi;
    dst[rb + 2048u + k] = hi;
    dst[rb + 4096u + k] = lo;
}

// B-side transpose+split: W [2048][N] fp32 -> dst[rowofs+n][ hi | lo(+2048) | hi(+4096) ]
__global__ __launch_bounds__(256)
void split_B_T_kernel(const float* __restrict__ W, int N, int rowofs, int which) {
    __nv_bfloat16* dst = (which == 0) ? g_Wqs : (which == 1 ? g_Wkvs : g_Wos);
    __shared__ float tile[32][33];
    const int k0 = blockIdx.y * 32;
    const int n0 = blockIdx.x * 32;
    const int t = threadIdx.x;
    const int ln = t & 31, lk = t >> 5;
    #pragma unroll
    for (int j = 0; j < 4; j++)
        tile[lk + j * 8][ln] = W[(size_t)(k0 + lk + j * 8) * N + n0 + ln];
    __syncthreads();
    const int on = t >> 3;                    // output n-row 0..31
    const int ok = (t & 7) * 4;               // k chunk
    float v[4];
    #pragma unroll
    for (int j = 0; j < 4; j++) v[j] = tile[ok + j][on];
    __nv_bfloat16 hi[4], lo[4];
    #pragma unroll
    for (int j = 0; j < 4; j++) split2(v[j], hi[j], lo[j]);
    __nv_bfloat162 h0 = __halves2bfloat162(hi[0], hi[1]);
    __nv_bfloat162 h1 = __halves2bfloat162(hi[2], hi[3]);
    __nv_bfloat162 l0 = __halves2bfloat162(lo[0], lo[1]);
    __nv_bfloat162 l1 = __halves2bfloat162(lo[2], lo[3]);
    size_t base = (size_t)(rowofs + n0 + on) * 6144u + k0 + ok;
    *(__nv_bfloat162*)(dst + base)            = h0;
    *(__nv_bfloat162*)(dst + base + 2)        = h1;
    *(__nv_bfloat162*)(dst + base + 2048)     = l0;
    *(__nv_bfloat162*)(dst + base + 2048 + 2) = l1;
    *(__nv_bfloat162*)(dst + base + 4096)     = h0;
    *(__nv_bfloat162*)(dst + base + 4096 + 2) = h1;
}

// ----------------------------- GEMM kernel -----------------------------------
// C[M][N] fp32 = A''[M][6144] * (B''[N][6144])^T, both bf16 K-major.
// which: 0=Q (full K), 1=KV partial (K slice per blockIdx.z), 2=O (gate epilogue)
__global__ __launch_bounds__(512)
void gemm_mma_kernel(int which, float* __restrict__ outp,
                     const float* __restrict__ gate, int N, int nk) {
    const __nv_bfloat16 *A, *B;
    float* C;
    if      (which == 0) { A = g_xs;  B = g_Wqs;  C = g_Q;  }
    else if (which == 1) { A = g_css; B = g_Wkvs; C = g_KVp + (size_t)blockIdx.z * (512u * 1024u); }
    else                 { A = g_ys;  B = g_Wos;  C = outp; }

    extern __shared__ char dynsmem[];
    const uint32_t sbase = (smem_u32(dynsmem) + 255u) & ~255u;

    const int t = threadIdx.x;
    const int lane = t & 31;
    const int wid  = t >> 5;
    const int m_base = blockIdx.y * BM;
    const int n_base = blockIdx.x * BN;
    const int kbeg   = blockIdx.z * (nk * BK);

    // warp grid: 2 along M (64 rows) x 8 along N (32 cols)
    const int wm = (wid >> 3) * 64;
    const int wn = (wid & 7) * 32;

    auto issue = [&](int s, int kglob) {
        uint32_t aT = sbase + s * STAGE_BYTES;
        uint32_t bT = aT + A_BYTES;
        #pragma unroll
        for (int j = 0; j < 2; j++) {            // A: 128 rows x 8 chunks
            int e = t + j * 512;
            int row = e >> 3, c = e & 7;
            cp16(aT + row * (ASTRIDE * 2) + c * 16,
                 A + (size_t)(m_base + row) * KK3 + kglob + c * 8);
        }
        #pragma unroll
        for (int j = 0; j < 4; j++) {            // B: 256 rows x 8 chunks
            int e = t + j * 512;
            int row = e >> 3, c = e & 7;
            cp16(bT + row * (ASTRIDE * 2) + c * 16,
                 B + (size_t)(n_base + row) * KK3 + kglob + c * 8);
        }
        cp_commit();
    };

    float acc[4][4][4];
    #pragma unroll
    for (int i = 0; i < 4; i++)
        #pragma unroll
        for (int j = 0; j < 4; j++)
            #pragma unroll
            for (int r = 0; r < 4; r++) acc[i][j][r] = 0.f;

    issue(0, kbeg);
    issue(1, kbeg + BK);

    // per-lane invariant smem offsets (bytes)
    const uint32_t a_off = (uint32_t)((wm + (lane & 15)) * (ASTRIDE * 2) + ((lane >> 4) * 8) * 2);
    const uint32_t b_off = (uint32_t)((wn + ((lane >> 4) & 1) * 8 + (lane & 7)) * (ASTRIDE * 2)
                                      + (((lane >> 3) & 1) * 8) * 2);

    for (int i = 0; i < nk; i++) {
        if (i < nk - 1) cp_wait1(); else cp_wait0();
        __syncthreads();
        if (i + 2 < nk) issue((i + 2) % 3, kbeg + (i + 2) * BK);

        const uint32_t aT = sbase + (i % 3) * STAGE_BYTES;
        const uint32_t bT = aT + A_BYTES;

        #pragma unroll
        for (int ks = 0; ks < 4; ks++) {
            const uint32_t kb = ks * 32;   // 16 bf16 = 32 bytes
            uint32_t a[4][4], bb[2][4];
            #pragma unroll
            for (int mi = 0; mi < 4; mi++) {
                uint32_t addr = aT + a_off + mi * (16 * ASTRIDE * 2) + kb;
                asm volatile("ldmatrix.sync.aligned.m8n8.x4.shared.b16 {%0,%1,%2,%3}, [%4];\n"
                    : "=r"(a[mi][0]), "=r"(a[mi][1]), "=r"(a[mi][2]), "=r"(a[mi][3])
                    : "r"(addr));
            }
            #pragma unroll
            for (int nn = 0; nn < 2; nn++) {
                uint32_t addr = bT + b_off + nn * (16 * ASTRIDE * 2) + kb;
                asm volatile("ldmatrix.sync.aligned.m8n8.x4.shared.b16 {%0,%1,%2,%3}, [%4];\n"
                    : "=r"(bb[nn][0]), "=r"(bb[nn][1]), "=r"(bb[nn][2]), "=r"(bb[nn][3])
                    : "r"(addr));
            }
            #pragma unroll
            for (int mi = 0; mi < 4; mi++)
                #pragma unroll
                for (int ni = 0; ni < 4; ni++) {
                    asm volatile(
                        "mma.sync.aligned.m16n8k16.row.col.f32.bf16.bf16.f32 "
                        "{%0,%1,%2,%3}, {%4,%5,%6,%7}, {%8,%9}, {%0,%1,%2,%3};\n"
                        : "+f"(acc[mi][ni][0]), "+f"(acc[mi][ni][1]),
                          "+f"(acc[mi][ni][2]), "+f"(acc[mi][ni][3])
                        : "r"(a[mi][0]), "r"(a[mi][1]), "r"(a[mi][2]), "r"(a[mi][3]),
                          "r"(bb[ni >> 1][(ni & 1) * 2]), "r"(bb[ni >> 1][(ni & 1) * 2 + 1]));
                }
        }
    }

    const float gs = (which == 2) ? tanhf(gate[0]) : 1.0f;
    const int g8 = lane >> 2;
    const int t4 = lane & 3;
    #pragma unroll
    for (int mi = 0; mi < 4; mi++)
        #pragma unroll
        for (int ni = 0; ni < 4; ni++) {
            size_t row0 = (size_t)m_base + wm + mi * 16 + g8;
            size_t col  = (size_t)n_base + wn + ni * 8 + t4 * 2;
            C[row0 * N + col]           = acc[mi][ni][0] * gs;
            C[row0 * N + col + 1]       = acc[mi][ni][1] * gs;
            C[(row0 + 8) * N + col]     = acc[mi][ni][2] * gs;
            C[(row0 + 8) * N + col + 1] = acc[mi][ni][3] * gs;
        }
}

// ------------------------- split-K reduce (KV) --------------------------------
__global__ void reduce_kv_kernel() {
    unsigned i = blockIdx.x * 256u + threadIdx.x;   // 0 .. 512*1024-1
    float s = 0.f;
    #pragma unroll
    for (int p = 0; p < KV_SPLITS; p++) s += g_KVp[(size_t)p * (512u * 1024u) + i];
    g_KV[i] = s;
}

// --------------------------- attention kernel --------------------------------
// 1 block per token. g_KV row: [(b*8+ch)*32 + latent][ k: g*128+d | v: 512+g*128+d ]
// Writes y in split layout into g_ys [2048][6144] = [hi|hi|lo].
__global__ __launch_bounds__(256)
void attn_kernel(const int* __restrict__ mask) {
    const int tg = blockIdx.x;
    const int b  = tg >> 10;
    const int ch = mask[tg];
    const size_t kvrow0 = (size_t)((b * 8 + ch) * 32);

    __shared__ float q_s[2048];
    __shared__ float attn_s[8][32];

    {
        const float4* src = (const float4*)(g_Q + (size_t)tg * 2048);
        float4* dst = (float4*)q_s;
        for (int i = threadIdx.x; i < 512; i += 256) dst[i] = src[i];
    }
    __syncthreads();

    const int wid = threadIdx.x >> 5;
    const int lane = threadIdx.x & 31;
    const float scale = 0.08838834764831845f;   // 1/sqrt(128)

    for (int hh = 0; hh < 2; hh++) {
        const int h = wid * 2 + hh;
        const int g = h >> 2;

        const float* krow = g_KV + (kvrow0 + lane) * 1024 + g * 128;
        const float* qh = q_s + h * 128;
        float s = 0.f;
        #pragma unroll 8
        for (int d = 0; d < 128; d += 4) {
            float4 k4 = *(const float4*)(krow + d);
            s += qh[d] * k4.x + qh[d + 1] * k4.y + qh[d + 2] * k4.z + qh[d + 3] * k4.w;
        }
        s *= scale;

        float m = s;
        #pragma unroll
        for (int o = 16; o; o >>= 1) m = fmaxf(m, __shfl_xor_sync(0xffffffffu, m, o));
        float e = __expf(s - m);
        float sum = e;
        #pragma unroll
        for (int o = 16; o; o >>= 1) sum += __shfl_xor_sync(0xffffffffu, sum, o);
        attn_s[wid][lane] = e / sum;
        __syncwarp();

        float4 acc = make_float4(0.f, 0.f, 0.f, 0.f);
        const float* vbase = g_KV + kvrow0 * 1024 + 512 + g * 128 + lane * 4;
        #pragma unroll
        for (int kl = 0; kl < 32; kl++) {
            float w = attn_s[wid][kl];
            float4 v4 = *(const float4*)(vbase + (size_t)kl * 1024);
            acc.x += w * v4.x; acc.y += w * v4.y; acc.z += w * v4.z; acc.w += w * v4.w;
        }

        float vals[4] = {acc.x, acc.y, acc.z, acc.w};
        __nv_bfloat16 hi[4], lo[4];
        #pragma unroll
        for (int i = 0; i < 4; i++) split2(vals[i], hi[i], lo[i]);
        __nv_bfloat162 hp0 = __halves2bfloat162(hi[0], hi[1]);
        __nv_bfloat162 hp1 = __halves2bfloat162(hi[2], hi[3]);
        __nv_bfloat162 lp0 = __halves2bfloat162(lo[0], lo[1]);
        __nv_bfloat162 lp1 = __halves2bfloat162(lo[2], lo[3]);
        size_t base = (size_t)tg * 6144u + h * 128 + lane * 4;
        *(__nv_bfloat162*)(g_ys + base)            = hp0;
        *(__nv_bfloat162*)(g_ys + base + 2)        = hp1;
        *(__nv_bfloat162*)(g_ys + base + 2048)     = hp0;
        *(__nv_bfloat162*)(g_ys + base + 2048 + 2) = hp1;
        *(__nv_bfloat162*)(g_ys + base + 4096)     = lp0;
        *(__nv_bfloat162*)(g_ys + base + 4096 + 2) = lp1;
        __syncwarp();
    }
}

// ------------------------------- launcher ------------------------------------
extern "C" void kernel_launch(void* const* d_in, const int* in_sizes, int n_in,
                              void* d_out, int out_size) {
    const float* x    = (const float*)d_in[0];   // (2,1024,2048)
    const float* cs   = (const float*)d_in[1];   // (2,8,32,2048)
    const int*   mask = (const int*)  d_in[2];   // (2,1024)
    const float* Wq   = (const float*)d_in[3];   // (2048,2048)
    const float* Wk   = (const float*)d_in[4];   // (2048,512)
    const float* Wv   = (const float*)d_in[5];   // (2048,512)
    const float* Wo   = (const float*)d_in[6];   // (2048,2048)
    const float* gate = (const float*)d_in[7];   // (1,)
    float* out = (float*)d_out;

    static bool attr_done = false;
    if (!attr_done) {
        cudaFuncSetAttribute(gemm_mma_kernel,
                             cudaFuncAttributeMaxDynamicSharedMemorySize, SMEM_DYN);
        attr_done = true;
    }

    // 1) splits (A-side plain, B-side transpose+split -> [N][K''] K-major)
    split_A_kernel<<<(2048u * 2048u) / 256u, 256>>>(x, 0);
    split_A_kernel<<<(512u  * 2048u) / 256u, 256>>>(cs, 1);
    split_B_T_kernel<<<dim3(64, 64), 256>>>(Wq, 2048, 0,   0);
    split_B_T_kernel<<<dim3(16, 64), 256>>>(Wk, 512,  0,   1);
    split_B_T_kernel<<<dim3(16, 64), 256>>>(Wv, 512,  512, 1);
    split_B_T_kernel<<<dim3(64, 64), 256>>>(Wo, 2048, 0,   2);

    // 2) Q = x @ Wq   (2048 x 2048), 128 CTAs, full K''
    gemm_mma_kernel<<<dim3(2048 / BN, 2048 / BM, 1), 512, SMEM_DYN>>>(0, nullptr, gate, 2048, KK3 / BK);

    // 3) [K|V] partials = channel_states @ [Wk|Wv]  (512 x 1024), split-K=8 -> 128 CTAs
    gemm_mma_kernel<<<dim3(1024 / BN, 512 / BM, KV_SPLITS), 512, SMEM_DYN>>>(1, nullptr, gate, 1024, KV_NK);
    reduce_kv_kernel<<<(512u * 1024u) / 256u, 256>>>();

    // 4) attention -> y (split layout)
    attn_kernel<<<2048, 256>>>(mask);

    // 5) out = (y @ Wo) * tanh(gate)   (2048 x 2048)
    gemm_mma_kernel<<<dim3(2048 / BN, 2048 / BM, 1), 512, SMEM_DYN>>>(2, out, gate, 2048, KK3 / BK);
}

// round 8
// speedup vs baseline: 1.5082x; 1.2374x over previous
#include <cuda_runtime.h>
#include <cuda_fp16.h>
#include <cstdint>
#include <math.h>

// ----------------------------------------------------------------------------
// GroupedSidechannelCrossAttention — fp16 split-2 mma.sync edition
//
//   Big GEMMs on tensor cores: mma.sync.m16n8k16 fp16 / fp32-accum,
//   CTA tile 128x256x64, 256 threads (8 warps, 2x4), warp tile 64x64,
//   3-stage cp.async pipeline, padded smem, both operands K-major.
//
//   Accuracy scheme (fp16 split-2, activation-side split):
//     act'' = [act_hi | act_lo]  (K''=4096),  W'' = [W_hi ; W_hi]
//     C = (act_hi + act_lo) @ W_hi  ->  error = act @ (W - fp16(W)) ~ 3e-4 rel.
//   W_hi stored once ([N][2048], K-major, transposed); B fetch uses k & 2047.
//
//   KV projection uses split-K=8 (128 CTAs) + tiny reduce kernel.
// ----------------------------------------------------------------------------

#define KK2 4096
#define BM  128
#define BN  256
#define BK  64
#define ASTRIDE 72                        // 64 + 8 pad (halves)
#define A_BYTES (128 * ASTRIDE * 2)       // 18432
#define B_BYTES (256 * ASTRIDE * 2)       // 36864
#define STAGE_BYTES (A_BYTES + B_BYTES)   // 55296
#define SMEM_DYN (3 * STAGE_BYTES + 256)
#define KV_SPLITS 8
#define KV_NK 8                           // 4096 / (8*64)

// ------------------------- device scratch (static) --------------------------
__device__ __half g_xs  [2048u * 4096u];  // x split        [2048][4096]=[hi|lo]
__device__ __half g_css [512u  * 4096u];  // ch.states split [512][4096]
__device__ __half g_ys  [2048u * 4096u];  // y split        [2048][4096]
__device__ __half g_Wqs [2048u * 2048u];  // Wq^T hi        [2048][2048]
__device__ __half g_Wkvs[1024u * 2048u];  // [Wk|Wv]^T hi   [1024][2048]
__device__ __half g_Wos [2048u * 2048u];  // Wo^T hi        [2048][2048]
__device__ float  g_Q   [2048u * 2048u];  // fp32 Q
__device__ float  g_KV  [512u  * 1024u];  // fp32 [k | v]
__device__ float  g_KVp [KV_SPLITS * 512u * 1024u]; // split-K partials

// ----------------------------- helpers --------------------------------------
__device__ __forceinline__ void split2h(float v, __half& hi, __half& lo) {
    hi = __float2half(v);
    lo = __float2half(v - __half2float(hi));
}
__device__ __forceinline__ uint32_t smem_u32(const void* p) {
    return (uint32_t)__cvta_generic_to_shared(p);
}
__device__ __forceinline__ void cp16(uint32_t dst, const void* src) {
    asm volatile("cp.async.cg.shared.global [%0], [%1], 16;\n" :: "r"(dst), "l"(src));
}
__device__ __forceinline__ void cp_commit() { asm volatile("cp.async.commit_group;\n" ::: "memory"); }
__device__ __forceinline__ void cp_wait0()  { asm volatile("cp.async.wait_group 0;\n" ::: "memory"); }
__device__ __forceinline__ void cp_wait1()  { asm volatile("cp.async.wait_group 1;\n" ::: "memory"); }

// --------------------------- split kernels -----------------------------------
// Activation side: src [R][2048] fp32 -> dst [R][4096] = [hi | lo]
__global__ void split_A_kernel(const float* __restrict__ src, int which) {
    __half* dst = (which == 0) ? g_xs : g_css;
    unsigned idx = blockIdx.x * 256u + threadIdx.x;
    unsigned r = idx >> 11;
    unsigned k = idx & 2047u;
    float v = src[idx];
    __half hi, lo; split2h(v, hi, lo);
    size_t rb = (size_t)r * 4096u;
    dst[rb + k]         = hi;
    dst[rb + 2048u + k] = lo;
}

// Weight side transpose: W [2048][N] fp32 -> dst[rowofs+n][k] = fp16(W[k][n])
__global__ __launch_bounds__(256)
void split_W_T_kernel(const float* __restrict__ W, int N, int rowofs, int which) {
    __half* dst = (which == 0) ? g_Wqs : (which == 1 ? g_Wkvs : g_Wos);
    __shared__ float tile[32][33];
    const int k0 = blockIdx.y * 32;
    const int n0 = blockIdx.x * 32;
    const int t = threadIdx.x;
    const int ln = t & 31, lk = t >> 5;
    #pragma unroll
    for (int j = 0; j < 4; j++)
        tile[lk + j * 8][ln] = W[(size_t)(k0 + lk + j * 8) * N + n0 + ln];
    __syncthreads();
    const int on = t >> 3;                    // output n-row 0..31
    const int ok = (t & 7) * 4;               // k chunk
    __half h[4];
    #pragma unroll
    for (int j = 0; j < 4; j++) h[j] = __float2half(tile[ok + j][on]);
    __half2 p0 = __halves2half2(h[0], h[1]);
    __half2 p1 = __halves2half2(h[2], h[3]);
    size_t base = (size_t)(rowofs + n0 + on) * 2048u + k0 + ok;
    *(__half2*)(dst + base)     = p0;
    *(__half2*)(dst + base + 2) = p1;
}

// ----------------------------- GEMM kernel -----------------------------------
// C[M][N] fp32 = act''[M][4096] * (W_hi[N][2048])^T with B k-index = k & 2047.
// which: 0=Q, 1=KV partial (K slice per blockIdx.z), 2=O (gate epilogue)
__global__ __launch_bounds__(256)
void gemm_mma_kernel(int which, float* __restrict__ outp,
                     const float* __restrict__ gate, int N, int nk) {
    const __half *A, *B;
    float* C;
    if      (which == 0) { A = g_xs;  B = g_Wqs;  C = g_Q;  }
    else if (which == 1) { A = g_css; B = g_Wkvs; C = g_KVp + (size_t)blockIdx.z * (512u * 1024u); }
    else                 { A = g_ys;  B = g_Wos;  C = outp; }

    extern __shared__ char dynsmem[];
    const uint32_t sbase = (smem_u32(dynsmem) + 255u) & ~255u;

    const int t = threadIdx.x;
    const int lane = t & 31;
    const int wid  = t >> 5;
    const int m_base = blockIdx.y * BM;
    const int n_base = blockIdx.x * BN;
    const int kbeg   = blockIdx.z * (nk * BK);

    // warp grid: 2 along M x 4 along N, warp tile 64x64
    const int wm = (wid >> 2) * 64;
    const int wn = (wid & 3) * 64;

    auto issue = [&](int s, int kglob) {
        uint32_t aT = sbase + s * STAGE_BYTES;
        uint32_t bT = aT + A_BYTES;
        #pragma unroll
        for (int j = 0; j < 4; j++) {            // A: 128 rows x 8 chunks of 16B
            int e = t + j * 256;
            int row = e >> 3, c = e & 7;
            cp16(aT + row * (ASTRIDE * 2) + c * 16,
                 A + (size_t)(m_base + row) * KK2 + kglob + c * 8);
        }
        const int kb = kglob & 2047;             // W_hi replicated across both halves
        #pragma unroll
        for (int j = 0; j < 8; j++) {            // B: 256 rows x 8 chunks of 16B
            int e = t + j * 256;
            int row = e >> 3, c = e & 7;
            cp16(bT + row * (ASTRIDE * 2) + c * 16,
                 B + (size_t)(n_base + row) * 2048u + kb + c * 8);
        }
        cp_commit();
    };

    float acc[4][8][4];
    #pragma unroll
    for (int i = 0; i < 4; i++)
        #pragma unroll
        for (int j = 0; j < 8; j++)
            #pragma unroll
            for (int r = 0; r < 4; r++) acc[i][j][r] = 0.f;

    issue(0, kbeg);
    issue(1, kbeg + BK);

    // per-lane invariant smem offsets (bytes)
    const uint32_t a_off = (uint32_t)((wm + (lane & 15)) * (ASTRIDE * 2) + ((lane >> 4) * 8) * 2);
    const uint32_t b_off = (uint32_t)((wn + ((lane >> 4) & 1) * 8 + (lane & 7)) * (ASTRIDE * 2)
                                      + (((lane >> 3) & 1) * 8) * 2);

    for (int i = 0; i < nk; i++) {
        if (i < nk - 1) cp_wait1(); else cp_wait0();
        __syncthreads();
        if (i + 2 < nk) issue((i + 2) % 3, kbeg + (i + 2) * BK);

        const uint32_t aT = sbase + (i % 3) * STAGE_BYTES;
        const uint32_t bT = aT + A_BYTES;

        #pragma unroll
        for (int ks = 0; ks < 4; ks++) {
            const uint32_t kb = ks * 32;   // 16 halves = 32 bytes
            uint32_t a[4][4], bb[4][4];
            #pragma unroll
            for (int mi = 0; mi < 4; mi++) {
                uint32_t addr = aT + a_off + mi * (16 * ASTRIDE * 2) + kb;
                asm volatile("ldmatrix.sync.aligned.m8n8.x4.shared.b16 {%0,%1,%2,%3}, [%4];\n"
                    : "=r"(a[mi][0]), "=r"(a[mi][1]), "=r"(a[mi][2]), "=r"(a[mi][3])
                    : "r"(addr));
            }
            #pragma unroll
            for (int nn = 0; nn < 4; nn++) {
                uint32_t addr = bT + b_off + nn * (16 * ASTRIDE * 2) + kb;
                asm volatile("ldmatrix.sync.aligned.m8n8.x4.shared.b16 {%0,%1,%2,%3}, [%4];\n"
                    : "=r"(bb[nn][0]), "=r"(bb[nn][1]), "=r"(bb[nn][2]), "=r"(bb[nn][3])
                    : "r"(addr));
            }
            #pragma unroll
            for (int mi = 0; mi < 4; mi++)
                #pragma unroll
                for (int ni = 0; ni < 8; ni++) {
                    asm volatile(
                        "mma.sync.aligned.m16n8k16.row.col.f32.f16.f16.f32 "
                        "{%0,%1,%2,%3}, {%4,%5,%6,%7}, {%8,%9}, {%0,%1,%2,%3};\n"
                        : "+f"(acc[mi][ni][0]), "+f"(acc[mi][ni][1]),
                          "+f"(acc[mi][ni][2]), "+f"(acc[mi][ni][3])
                        : "r"(a[mi][0]), "r"(a[mi][1]), "r"(a[mi][2]), "r"(a[mi][3]),
                          "r"(bb[ni >> 1][(ni & 1) * 2]), "r"(bb[ni >> 1][(ni & 1) * 2 + 1]));
                }
        }
    }

    const float gs = (which == 2) ? tanhf(gate[0]) : 1.0f;
    const int g8 = lane >> 2;
    const int t4 = lane & 3;
    #pragma unroll
    for (int mi = 0; mi < 4; mi++)
        #pragma unroll
        for (int ni = 0; ni < 8; ni++) {
            size_t row0 = (size_t)m_base + wm + mi * 16 + g8;
            size_t col  = (size_t)n_base + wn + ni * 8 + t4 * 2;
            C[row0 * N + col]           = acc[mi][ni][0] * gs;
            C[row0 * N + col + 1]       = acc[mi][ni][1] * gs;
            C[(row0 + 8) * N + col]     = acc[mi][ni][2] * gs;
            C[(row0 + 8) * N + col + 1] = acc[mi][ni][3] * gs;
        }
}

// ------------------------- split-K reduce (KV) --------------------------------
__global__ void reduce_kv_kernel() {
    unsigned i = blockIdx.x * 256u + threadIdx.x;
    float s = 0.f;
    #pragma unroll
    for (int p = 0; p < KV_SPLITS; p++) s += g_KVp[(size_t)p * (512u * 1024u) + i];
    g_KV[i] = s;
}

// --------------------------- attention kernel --------------------------------
// 1 block per token. g_KV row: [(b*8+ch)*32 + latent][ k: g*128+d | v: 512+g*128+d ]
// Writes y in split layout into g_ys [2048][4096] = [hi|lo].
__global__ __launch_bounds__(256)
void attn_kernel(const int* __restrict__ mask) {
    const int tg = blockIdx.x;
    const int b  = tg >> 10;
    const int ch = mask[tg];
    const size_t kvrow0 = (size_t)((b * 8 + ch) * 32);

    __shared__ float q_s[2048];
    __shared__ float attn_s[8][32];

    {
        const float4* src = (const float4*)(g_Q + (size_t)tg * 2048);
        float4* dst = (float4*)q_s;
        for (int i = threadIdx.x; i < 512; i += 256) dst[i] = src[i];
    }
    __syncthreads();

    const int wid = threadIdx.x >> 5;
    const int lane = threadIdx.x & 31;
    const float scale = 0.08838834764831845f;   // 1/sqrt(128)

    for (int hh = 0; hh < 2; hh++) {
        const int h = wid * 2 + hh;
        const int g = h >> 2;

        const float* krow = g_KV + (kvrow0 + lane) * 1024 + g * 128;
        const float* qh = q_s + h * 128;
        float s = 0.f;
        #pragma unroll 8
        for (int d = 0; d < 128; d += 4) {
            float4 k4 = *(const float4*)(krow + d);
            s += qh[d] * k4.x + qh[d + 1] * k4.y + qh[d + 2] * k4.z + qh[d + 3] * k4.w;
        }
        s *= scale;

        float m = s;
        #pragma unroll
        for (int o = 16; o; o >>= 1) m = fmaxf(m, __shfl_xor_sync(0xffffffffu, m, o));
        float e = __expf(s - m);
        float sum = e;
        #pragma unroll
        for (int o = 16; o; o >>= 1) sum += __shfl_xor_sync(0xffffffffu, sum, o);
        attn_s[wid][lane] = e / sum;
        __syncwarp();

        float4 acc = make_float4(0.f, 0.f, 0.f, 0.f);
        const float* vbase = g_KV + kvrow0 * 1024 + 512 + g * 128 + lane * 4;
        #pragma unroll
        for (int kl = 0; kl < 32; kl++) {
            float w = attn_s[wid][kl];
            float4 v4 = *(const float4*)(vbase + (size_t)kl * 1024);
            acc.x += w * v4.x; acc.y += w * v4.y; acc.z += w * v4.z; acc.w += w * v4.w;
        }

        float vals[4] = {acc.x, acc.y, acc.z, acc.w};
        __half hi[4], lo[4];
        #pragma unroll
        for (int i = 0; i < 4; i++) split2h(vals[i], hi[i], lo[i]);
        __half2 hp0 = __halves2half2(hi[0], hi[1]);
        __half2 hp1 = __halves2half2(hi[2], hi[3]);
        __half2 lp0 = __halves2half2(lo[0], lo[1]);
        __half2 lp1 = __halves2half2(lo[2], lo[3]);
        size_t base = (size_t)tg * 4096u + h * 128 + lane * 4;
        *(__half2*)(g_ys + base)            = hp0;
        *(__half2*)(g_ys + base + 2)        = hp1;
        *(__half2*)(g_ys + base + 2048)     = lp0;
        *(__half2*)(g_ys + base + 2048 + 2) = lp1;
        __syncwarp();
    }
}

// ------------------------------- launcher ------------------------------------
extern "C" void kernel_launch(void* const* d_in, const int* in_sizes, int n_in,
                              void* d_out, int out_size) {
    const float* x    = (const float*)d_in[0];   // (2,1024,2048)
    const float* cs   = (const float*)d_in[1];   // (2,8,32,2048)
    const int*   mask = (const int*)  d_in[2];   // (2,1024)
    const float* Wq   = (const float*)d_in[3];   // (2048,2048)
    const float* Wk   = (const float*)d_in[4];   // (2048,512)
    const float* Wv   = (const float*)d_in[5];   // (2048,512)
    const float* Wo   = (const float*)d_in[6];   // (2048,2048)
    const float* gate = (const float*)d_in[7];   // (1,)
    float* out = (float*)d_out;

    static bool attr_done = false;
    if (!attr_done) {
        cudaFuncSetAttribute(gemm_mma_kernel,
                             cudaFuncAttributeMaxDynamicSharedMemorySize, SMEM_DYN);
        attr_done = true;
    }

    // 1) splits (activation split-2, weight hi-only transpose)
    split_A_kernel<<<(2048u * 2048u) / 256u, 256>>>(x, 0);
    split_A_kernel<<<(512u  * 2048u) / 256u, 256>>>(cs, 1);
    split_W_T_kernel<<<dim3(64, 64), 256>>>(Wq, 2048, 0,   0);
    split_W_T_kernel<<<dim3(16, 64), 256>>>(Wk, 512,  0,   1);
    split_W_T_kernel<<<dim3(16, 64), 256>>>(Wv, 512,  512, 1);
    split_W_T_kernel<<<dim3(64, 64), 256>>>(Wo, 2048, 0,   2);

    // 2) Q = x @ Wq   (2048 x 2048), 128 CTAs, K''=4096
    gemm_mma_kernel<<<dim3(2048 / BN, 2048 / BM, 1), 256, SMEM_DYN>>>(0, nullptr, gate, 2048, KK2 / BK);

    // 3) [K|V] partials = channel_states @ [Wk|Wv]  (512 x 1024), split-K=8 -> 128 CTAs
    gemm_mma_kernel<<<dim3(1024 / BN, 512 / BM, KV_SPLITS), 256, SMEM_DYN>>>(1, nullptr, gate, 1024, KV_NK);
    reduce_kv_kernel<<<(512u * 1024u) / 256u, 256>>>();

    // 4) attention -> y (split layout)
    attn_kernel<<<2048, 256>>>(mask);

    // 5) out = (y @ Wo) * tanh(gate)   (2048 x 2048)
    gemm_mma_kernel<<<dim3(2048 / BN, 2048 / BM, 1), 256, SMEM_DYN>>>(2, out, gate, 2048, KK2 / BK);
}

// round 10
// speedup vs baseline: 2.0988x; 1.3916x over previous
#include <cuda_runtime.h>
#include <cuda_fp16.h>
#include <cstdint>
#include <math.h>

// ----------------------------------------------------------------------------
// GroupedSidechannelCrossAttention — pure fp16 mma.sync edition
//
//   All three projections as plain fp16 GEMMs (fp32 accum), K = 2048:
//   error budget: W-rounding (measured 3.7e-4 in R8) + act-rounding of the
//   same magnitude, independent -> ~5.2e-4 total, under the 1e-3 threshold.
//
//   GEMM config = the empirically fastest from R6: CTA tile 128x256x64,
//   512 threads (16 warps, 2x8), warp tile 64x32, 3-stage cp.async pipeline,
//   padded smem (72-half stride, conflict-free), both operands K-major
//   (weights stored transposed in fp16), ldmatrix x4 non-trans everywhere.
//
//   KV projection uses split-K=8 (128 CTAs) + tiny reduce kernel.
//   Attention internals stay fp32 (Q and KV buffers are fp32).
// ----------------------------------------------------------------------------

#define KK  2048
#define BM  128
#define BN  256
#define BK  64
#define ASTRIDE 72                        // 64 + 8 pad (halves)
#define A_BYTES (128 * ASTRIDE * 2)       // 18432
#define B_BYTES (256 * ASTRIDE * 2)       // 36864
#define STAGE_BYTES (A_BYTES + B_BYTES)   // 55296
#define SMEM_DYN (3 * STAGE_BYTES + 256)
#define KV_SPLITS 8
#define KV_NK 4                           // 2048 / (8*64)

// ------------------------- device scratch (static) --------------------------
__device__ __half g_xh  [2048u * 2048u];  // x fp16          [2048][2048]
__device__ __half g_csh [512u  * 2048u];  // ch.states fp16  [512][2048]
__device__ __half g_yh  [2048u * 2048u];  // y fp16          [2048][2048]
__device__ __half g_Wqh [2048u * 2048u];  // Wq^T fp16       [2048][2048]
__device__ __half g_Wkvh[1024u * 2048u];  // [Wk|Wv]^T fp16  [1024][2048]
__device__ __half g_Woh [2048u * 2048u];  // Wo^T fp16       [2048][2048]
__device__ float  g_Q   [2048u * 2048u];  // fp32 Q
__device__ float  g_KV  [512u  * 1024u];  // fp32 [k | v]
__device__ float  g_KVp [KV_SPLITS * 512u * 1024u]; // split-K partials

// ----------------------------- helpers --------------------------------------
__device__ __forceinline__ uint32_t smem_u32(const void* p) {
    return (uint32_t)__cvta_generic_to_shared(p);
}
__device__ __forceinline__ void cp16(uint32_t dst, const void* src) {
    asm volatile("cp.async.cg.shared.global [%0], [%1], 16;\n" :: "r"(dst), "l"(src));
}
__device__ __forceinline__ void cp_commit() { asm volatile("cp.async.commit_group;\n" ::: "memory"); }
__device__ __forceinline__ void cp_wait0()  { asm volatile("cp.async.wait_group 0;\n" ::: "memory"); }
__device__ __forceinline__ void cp_wait1()  { asm volatile("cp.async.wait_group 1;\n" ::: "memory"); }

// --------------------------- convert kernels ---------------------------------
// Activations: fp32 [R][2048] -> fp16, vectorized 4/thread
__global__ void conv_A_kernel(const float* __restrict__ src, int which) {
    __half* dst = (which == 0) ? g_xh : g_csh;
    unsigned i = (blockIdx.x * 256u + threadIdx.x) * 4u;
    float4 v = *(const float4*)(src + i);
    __half2 p0 = __floats2half2_rn(v.x, v.y);
    __half2 p1 = __floats2half2_rn(v.z, v.w);
    *(__half2*)(dst + i)     = p0;
    *(__half2*)(dst + i + 2) = p1;
}

// Weights: W [2048][N] fp32 -> dst[rowofs+n][k] = fp16(W[k][n])  (transpose)
__global__ __launch_bounds__(256)
void conv_W_T_kernel(const float* __restrict__ W, int N, int rowofs, int which) {
    __half* dst = (which == 0) ? g_Wqh : (which == 1 ? g_Wkvh : g_Woh);
    __shared__ float tile[32][33];
    const int k0 = blockIdx.y * 32;
    const int n0 = blockIdx.x * 32;
    const int t = threadIdx.x;
    const int ln = t & 31, lk = t >> 5;
    #pragma unroll
    for (int j = 0; j < 4; j++)
        tile[lk + j * 8][ln] = W[(size_t)(k0 + lk + j * 8) * N + n0 + ln];
    __syncthreads();
    const int on = t >> 3;                    // output n-row 0..31
    const int ok = (t & 7) * 4;               // k chunk
    __half2 p0 = __floats2half2_rn(tile[ok][on],     tile[ok + 1][on]);
    __half2 p1 = __floats2half2_rn(tile[ok + 2][on], tile[ok + 3][on]);
    size_t base = (size_t)(rowofs + n0 + on) * 2048u + k0 + ok;
    *(__half2*)(dst + base)     = p0;
    *(__half2*)(dst + base + 2) = p1;
}

// ----------------------------- GEMM kernel -----------------------------------
// C[M][N] fp32 = A[M][2048] * (W[N][2048])^T, fp16 in / fp32 accum.
// which: 0=Q, 1=KV partial (K slice per blockIdx.z), 2=O (gate epilogue)
__global__ __launch_bounds__(512)
void gemm_mma_kernel(int which, float* __restrict__ outp,
                     const float* __restrict__ gate, int N, int nk) {
    const __half *A, *B;
    float* C;
    if      (which == 0) { A = g_xh;  B = g_Wqh;  C = g_Q;  }
    else if (which == 1) { A = g_csh; B = g_Wkvh; C = g_KVp + (size_t)blockIdx.z * (512u * 1024u); }
    else                 { A = g_yh;  B = g_Woh;  C = outp; }

    extern __shared__ char dynsmem[];
    const uint32_t sbase = (smem_u32(dynsmem) + 255u) & ~255u;

    const int t = threadIdx.x;
    const int lane = t & 31;
    const int wid  = t >> 5;
    const int m_base = blockIdx.y * BM;
    const int n_base = blockIdx.x * BN;
    const int kbeg   = blockIdx.z * (nk * BK);

    // warp grid: 2 along M (64 rows) x 8 along N (32 cols)
    const int wm = (wid >> 3) * 64;
    const int wn = (wid & 7) * 32;

    auto issue = [&](int s, int kglob) {
        uint32_t aT = sbase + s * STAGE_BYTES;
        uint32_t bT = aT + A_BYTES;
        #pragma unroll
        for (int j = 0; j < 2; j++) {            // A: 128 rows x 8 chunks of 16B
            int e = t + j * 512;
            int row = e >> 3, c = e & 7;
            cp16(aT + row * (ASTRIDE * 2) + c * 16,
                 A + (size_t)(m_base + row) * KK + kglob + c * 8);
        }
        #pragma unroll
        for (int j = 0; j < 4; j++) {            // B: 256 rows x 8 chunks of 16B
            int e = t + j * 512;
            int row = e >> 3, c = e & 7;
            cp16(bT + row * (ASTRIDE * 2) + c * 16,
                 B + (size_t)(n_base + row) * 2048u + kglob + c * 8);
        }
        cp_commit();
    };

    float acc[4][4][4];
    #pragma unroll
    for (int i = 0; i < 4; i++)
        #pragma unroll
        for (int j = 0; j < 4; j++)
            #pragma unroll
            for (int r = 0; r < 4; r++) acc[i][j][r] = 0.f;

    issue(0, kbeg);
    issue(1, kbeg + BK);

    // per-lane invariant smem offsets (bytes)
    const uint32_t a_off = (uint32_t)((wm + (lane & 15)) * (ASTRIDE * 2) + ((lane >> 4) * 8) * 2);
    const uint32_t b_off = (uint32_t)((wn + ((lane >> 4) & 1) * 8 + (lane & 7)) * (ASTRIDE * 2)
                                      + (((lane >> 3) & 1) * 8) * 2);

    for (int i = 0; i < nk; i++) {
        if (i < nk - 1) cp_wait1(); else cp_wait0();
        __syncthreads();
        if (i + 2 < nk) issue((i + 2) % 3, kbeg + (i + 2) * BK);

        const uint32_t aT = sbase + (i % 3) * STAGE_BYTES;
        const uint32_t bT = aT + A_BYTES;

        #pragma unroll
        for (int ks = 0; ks < 4; ks++) {
            const uint32_t kb = ks * 32;   // 16 halves = 32 bytes
            uint32_t a[4][4], bb[2][4];
            #pragma unroll
            for (int mi = 0; mi < 4; mi++) {
                uint32_t addr = aT + a_off + mi * (16 * ASTRIDE * 2) + kb;
                asm volatile("ldmatrix.sync.aligned.m8n8.x4.shared.b16 {%0,%1,%2,%3}, [%4];\n"
                    : "=r"(a[mi][0]), "=r"(a[mi][1]), "=r"(a[mi][2]), "=r"(a[mi][3])
                    : "r"(addr));
            }
            #pragma unroll
            for (int nn = 0; nn < 2; nn++) {
                uint32_t addr = bT + b_off + nn * (16 * ASTRIDE * 2) + kb;
                asm volatile("ldmatrix.sync.aligned.m8n8.x4.shared.b16 {%0,%1,%2,%3}, [%4];\n"
                    : "=r"(bb[nn][0]), "=r"(bb[nn][1]), "=r"(bb[nn][2]), "=r"(bb[nn][3])
                    : "r"(addr));
            }
            #pragma unroll
            for (int mi = 0; mi < 4; mi++)
                #pragma unroll
                for (int ni = 0; ni < 4; ni++) {
                    asm volatile(
                        "mma.sync.aligned.m16n8k16.row.col.f32.f16.f16.f32 "
                        "{%0,%1,%2,%3}, {%4,%5,%6,%7}, {%8,%9}, {%0,%1,%2,%3};\n"
                        : "+f"(acc[mi][ni][0]), "+f"(acc[mi][ni][1]),
                          "+f"(acc[mi][ni][2]), "+f"(acc[mi][ni][3])
                        : "r"(a[mi][0]), "r"(a[mi][1]), "r"(a[mi][2]), "r"(a[mi][3]),
                          "r"(bb[ni >> 1][(ni & 1) * 2]), "r"(bb[ni >> 1][(ni & 1) * 2 + 1]));
                }
        }
    }

    const float gs = (which == 2) ? tanhf(gate[0]) : 1.0f;
    const int g8 = lane >> 2;
    const int t4 = lane & 3;
    #pragma unroll
    for (int mi = 0; mi < 4; mi++)
        #pragma unroll
        for (int ni = 0; ni < 4; ni++) {
            size_t row0 = (size_t)m_base + wm + mi * 16 + g8;
            size_t col  = (size_t)n_base + wn + ni * 8 + t4 * 2;
            C[row0 * N + col]           = acc[mi][ni][0] * gs;
            C[row0 * N + col + 1]       = acc[mi][ni][1] * gs;
            C[(row0 + 8) * N + col]     = acc[mi][ni][2] * gs;
            C[(row0 + 8) * N + col + 1] = acc[mi][ni][3] * gs;
        }
}

// ------------------------- split-K reduce (KV) --------------------------------
__global__ void reduce_kv_kernel() {
    unsigned i = blockIdx.x * 256u + threadIdx.x;
    float s = 0.f;
    #pragma unroll
    for (int p = 0; p < KV_SPLITS; p++) s += g_KVp[(size_t)p * (512u * 1024u) + i];
    g_KV[i] = s;
}

// --------------------------- attention kernel --------------------------------
// 1 block per token. g_KV row: [(b*8+ch)*32 + latent][ k: g*128+d | v: 512+g*128+d ]
// Writes y as fp16 into g_yh [2048][2048].
__global__ __launch_bounds__(256)
void attn_kernel(const int* __restrict__ mask) {
    const int tg = blockIdx.x;
    const int b  = tg >> 10;
    const int ch = mask[tg];
    const size_t kvrow0 = (size_t)((b * 8 + ch) * 32);

    __shared__ float q_s[2048];
    __shared__ float attn_s[8][32];

    {
        const float4* src = (const float4*)(g_Q + (size_t)tg * 2048);
        float4* dst = (float4*)q_s;
        for (int i = threadIdx.x; i < 512; i += 256) dst[i] = src[i];
    }
    __syncthreads();

    const int wid = threadIdx.x >> 5;
    const int lane = threadIdx.x & 31;
    const float scale = 0.08838834764831845f;   // 1/sqrt(128)

    for (int hh = 0; hh < 2; hh++) {
        const int h = wid * 2 + hh;
        const int g = h >> 2;

        const float* krow = g_KV + (kvrow0 + lane) * 1024 + g * 128;
        const float* qh = q_s + h * 128;
        float s = 0.f;
        #pragma unroll 8
        for (int d = 0; d < 128; d += 4) {
            float4 k4 = *(const float4*)(krow + d);
            s += qh[d] * k4.x + qh[d + 1] * k4.y + qh[d + 2] * k4.z + qh[d + 3] * k4.w;
        }
        s *= scale;

        float m = s;
        #pragma unroll
        for (int o = 16; o; o >>= 1) m = fmaxf(m, __shfl_xor_sync(0xffffffffu, m, o));
        float e = __expf(s - m);
        float sum = e;
        #pragma unroll
        for (int o = 16; o; o >>= 1) sum += __shfl_xor_sync(0xffffffffu, sum, o);
        attn_s[wid][lane] = e / sum;
        __syncwarp();

        float4 acc = make_float4(0.f, 0.f, 0.f, 0.f);
        const float* vbase = g_KV + kvrow0 * 1024 + 512 + g * 128 + lane * 4;
        #pragma unroll
        for (int kl = 0; kl < 32; kl++) {
            float w = attn_s[wid][kl];
            float4 v4 = *(const float4*)(vbase + (size_t)kl * 1024);
            acc.x += w * v4.x; acc.y += w * v4.y; acc.z += w * v4.z; acc.w += w * v4.w;
        }

        __half2 p0 = __floats2half2_rn(acc.x, acc.y);
        __half2 p1 = __floats2half2_rn(acc.z, acc.w);
        size_t base = (size_t)tg * 2048u + h * 128 + lane * 4;
        *(__half2*)(g_yh + base)     = p0;
        *(__half2*)(g_yh + base + 2) = p1;
        __syncwarp();
    }
}

// ------------------------------- launcher ------------------------------------
extern "C" void kernel_launch(void* const* d_in, const int* in_sizes, int n_in,
                              void* d_out, int out_size) {
    const float* x    = (const float*)d_in[0];   // (2,1024,2048)
    const float* cs   = (const float*)d_in[1];   // (2,8,32,2048)
    const int*   mask = (const int*)  d_in[2];   // (2,1024)
    const float* Wq   = (const float*)d_in[3];   // (2048,2048)
    const float* Wk   = (const float*)d_in[4];   // (2048,512)
    const float* Wv   = (const float*)d_in[5];   // (2048,512)
    const float* Wo   = (const float*)d_in[6];   // (2048,2048)
    const float* gate = (const float*)d_in[7];   // (1,)
    float* out = (float*)d_out;

    static bool attr_done = false;
    if (!attr_done) {
        cudaFuncSetAttribute(gemm_mma_kernel,
                             cudaFuncAttributeMaxDynamicSharedMemorySize, SMEM_DYN);
        attr_done = true;
    }

    // 1) converts (activations cast, weights cast+transpose)
    conv_A_kernel<<<(2048u * 2048u) / 1024u, 256>>>(x, 0);
    conv_A_kernel<<<(512u  * 2048u) / 1024u, 256>>>(cs, 1);
    conv_W_T_kernel<<<dim3(64, 64), 256>>>(Wq, 2048, 0,   0);
    conv_W_T_kernel<<<dim3(16, 64), 256>>>(Wk, 512,  0,   1);
    conv_W_T_kernel<<<dim3(16, 64), 256>>>(Wv, 512,  512, 1);
    conv_W_T_kernel<<<dim3(64, 64), 256>>>(Wo, 2048, 0,   2);

    // 2) Q = x @ Wq   (2048 x 2048), 128 CTAs, K=2048
    gemm_mma_kernel<<<dim3(2048 / BN, 2048 / BM, 1), 512, SMEM_DYN>>>(0, nullptr, gate, 2048, KK / BK);

    // 3) [K|V] partials = channel_states @ [Wk|Wv]  (512 x 1024), split-K=8 -> 128 CTAs
    gemm_mma_kernel<<<dim3(1024 / BN, 512 / BM, KV_SPLITS), 512, SMEM_DYN>>>(1, nullptr, gate, 1024, KV_NK);
    reduce_kv_kernel<<<(512u * 1024u) / 256u, 256>>>();

    // 4) attention -> y (fp16)
    attn_kernel<<<2048, 256>>>(mask);

    // 5) out = (y @ Wo) * tanh(gate)   (2048 x 2048)
    gemm_mma_kernel<<<dim3(2048 / BN, 2048 / BM, 1), 512, SMEM_DYN>>>(2, out, gate, 2048, KK / BK);
}

// round 12
// speedup vs baseline: 2.1924x; 1.0446x over previous
#include <cuda_runtime.h>
#include <cuda_fp16.h>
#include <cstdint>
#include <math.h>

// ----------------------------------------------------------------------------
// GroupedSidechannelCrossAttention — pure fp16 mma.sync, consolidated launches
//
//   All three projections as plain fp16 GEMMs (fp32 accum), K = 2048.
//   Error budget (measured): 5.2e-4 total vs 1e-3 threshold.
//
//   GEMM: CTA tile 128x256x64, 512 threads (16 warps, 2x8), warp tile 64x32,
//   4-stage cp.async pipeline (221KB smem, 1 CTA/SM), padded smem
//   (72-half stride), both operands K-major, ldmatrix x4 non-trans.
//
//   Launch graph (6 nodes): conv_all -> Q gemm -> KV gemm(splitK=8) ->
//   reduce -> attn -> O gemm.
// ----------------------------------------------------------------------------

#define KK  2048
#define BM  128
#define BN  256
#define BK  64
#define ASTRIDE 72                        // 64 + 8 pad (halves)
#define A_BYTES (128 * ASTRIDE * 2)       // 18432
#define B_BYTES (256 * ASTRIDE * 2)       // 36864
#define STAGE_BYTES (A_BYTES + B_BYTES)   // 55296
#define NSTAGE 4
#define SMEM_DYN (NSTAGE * STAGE_BYTES + 256)   // 221440
#define KV_SPLITS 8
#define KV_NK 4                           // 2048 / (8*64)

// ------------------------- device scratch (static) --------------------------
__device__ __half g_xh  [2048u * 2048u];  // x fp16          [2048][2048]
__device__ __half g_csh [512u  * 2048u];  // ch.states fp16  [512][2048]
__device__ __half g_yh  [2048u * 2048u];  // y fp16          [2048][2048]
__device__ __half g_Wqh [2048u * 2048u];  // Wq^T fp16       [2048][2048]
__device__ __half g_Wkvh[1024u * 2048u];  // [Wk|Wv]^T fp16  [1024][2048]
__device__ __half g_Woh [2048u * 2048u];  // Wo^T fp16       [2048][2048]
__device__ float  g_Q   [2048u * 2048u];  // fp32 Q
__device__ float  g_KV  [512u  * 1024u];  // fp32 [k | v]
__device__ float  g_KVp [KV_SPLITS * 512u * 1024u]; // split-K partials

// ----------------------------- helpers --------------------------------------
__device__ __forceinline__ uint32_t smem_u32(const void* p) {
    return (uint32_t)__cvta_generic_to_shared(p);
}
__device__ __forceinline__ void cp16(uint32_t dst, const void* src) {
    asm volatile("cp.async.cg.shared.global [%0], [%1], 16;\n" :: "r"(dst), "l"(src));
}
__device__ __forceinline__ void cp_commit() { asm volatile("cp.async.commit_group;\n" ::: "memory"); }
__device__ __forceinline__ void cp_wait0()  { asm volatile("cp.async.wait_group 0;\n" ::: "memory"); }
__device__ __forceinline__ void cp_wait1()  { asm volatile("cp.async.wait_group 1;\n" ::: "memory"); }
__device__ __forceinline__ void cp_wait2()  { asm volatile("cp.async.wait_group 2;\n" ::: "memory"); }

// --------------------------- consolidated converts ---------------------------
// One kernel does every fp32->fp16 conversion + weight transpose.
// Block ranges:
//   [0, 4096)        : x cast          (4 elems/thread)
//   [4096, 5120)     : cs cast
//   [5120, 9216)     : Wq transpose    (32x32 tiles, 64 wide)
//   [9216, 10240)    : Wk transpose    (16 wide)  -> rows [0,512)   of g_Wkvh
//   [10240, 11264)   : Wv transpose    (16 wide)  -> rows [512,1024)
//   [11264, 15360)   : Wo transpose
__global__ __launch_bounds__(256)
void conv_all_kernel(const float* __restrict__ x,  const float* __restrict__ cs,
                     const float* __restrict__ Wq, const float* __restrict__ Wk,
                     const float* __restrict__ Wv, const float* __restrict__ Wo) {
    __shared__ float tile[32][33];
    const int bid = blockIdx.x;
    const int t = threadIdx.x;

    if (bid < 5120) {                      // ---- plain casts ----
        const float* src; __half* dst; unsigned base;
        if (bid < 4096) { src = x;  dst = g_xh;  base = (unsigned)bid * 1024u; }
        else            { src = cs; dst = g_csh; base = (unsigned)(bid - 4096) * 1024u; }
        unsigned i = base + t * 4u;
        float4 v = *(const float4*)(src + i);
        *(__half2*)(dst + i)     = __floats2half2_rn(v.x, v.y);
        *(__half2*)(dst + i + 2) = __floats2half2_rn(v.z, v.w);
        return;
    }

    // ---- weight transposes ----
    const float* W; __half* dst; int N, rowofs, local;
    if (bid < 9216)       { W = Wq; dst = g_Wqh;  N = 2048; rowofs = 0;   local = bid - 5120;  }
    else if (bid < 10240) { W = Wk; dst = g_Wkvh; N = 512;  rowofs = 0;   local = bid - 9216;  }
    else if (bid < 11264) { W = Wv; dst = g_Wkvh; N = 512;  rowofs = 512; local = bid - 10240; }
    else                  { W = Wo; dst = g_Woh;  N = 2048; rowofs = 0;   local = bid - 11264; }
    const int wtiles = N >> 5;
    const int n0 = (local % wtiles) * 32;
    const int k0 = (local / wtiles) * 32;

    const int ln = t & 31, lk = t >> 5;
    #pragma unroll
    for (int j = 0; j < 4; j++)
        tile[lk + j * 8][ln] = W[(size_t)(k0 + lk + j * 8) * N + n0 + ln];
    __syncthreads();
    const int on = t >> 3;                    // output n-row 0..31
    const int ok = (t & 7) * 4;               // k chunk
    __half2 p0 = __floats2half2_rn(tile[ok][on],     tile[ok + 1][on]);
    __half2 p1 = __floats2half2_rn(tile[ok + 2][on], tile[ok + 3][on]);
    size_t base = (size_t)(rowofs + n0 + on) * 2048u + k0 + ok;
    *(__half2*)(dst + base)     = p0;
    *(__half2*)(dst + base + 2) = p1;
}

// ----------------------------- GEMM kernel -----------------------------------
// C[M][N] fp32 = A[M][2048] * (W[N][2048])^T, fp16 in / fp32 accum.
// which: 0=Q, 1=KV partial (K slice per blockIdx.z), 2=O (gate epilogue)
__global__ __launch_bounds__(512)
void gemm_mma_kernel(int which, float* __restrict__ outp,
                     const float* __restrict__ gate, int N, int nk) {
    const __half *A, *B;
    float* C;
    if      (which == 0) { A = g_xh;  B = g_Wqh;  C = g_Q;  }
    else if (which == 1) { A = g_csh; B = g_Wkvh; C = g_KVp + (size_t)blockIdx.z * (512u * 1024u); }
    else                 { A = g_yh;  B = g_Woh;  C = outp; }

    extern __shared__ char dynsmem[];
    const uint32_t sbase = (smem_u32(dynsmem) + 255u) & ~255u;

    const int t = threadIdx.x;
    const int lane = t & 31;
    const int wid  = t >> 5;
    const int m_base = blockIdx.y * BM;
    const int n_base = blockIdx.x * BN;
    const int kbeg   = blockIdx.z * (nk * BK);

    // warp grid: 2 along M (64 rows) x 8 along N (32 cols)
    const int wm = (wid >> 3) * 64;
    const int wn = (wid & 7) * 32;

    auto issue = [&](int s, int kglob) {
        uint32_t aT = sbase + s * STAGE_BYTES;
        uint32_t bT = aT + A_BYTES;
        #pragma unroll
        for (int j = 0; j < 2; j++) {            // A: 128 rows x 8 chunks of 16B
            int e = t + j * 512;
            int row = e >> 3, c = e & 7;
            cp16(aT + row * (ASTRIDE * 2) + c * 16,
                 A + (size_t)(m_base + row) * KK + kglob + c * 8);
        }
        #pragma unroll
        for (int j = 0; j < 4; j++) {            // B: 256 rows x 8 chunks of 16B
            int e = t + j * 512;
            int row = e >> 3, c = e & 7;
            cp16(bT + row * (ASTRIDE * 2) + c * 16,
                 B + (size_t)(n_base + row) * 2048u + kglob + c * 8);
        }
        cp_commit();
    };

    float acc[4][4][4];
    #pragma unroll
    for (int i = 0; i < 4; i++)
        #pragma unroll
        for (int j = 0; j < 4; j++)
            #pragma unroll
            for (int r = 0; r < 4; r++) acc[i][j][r] = 0.f;

    // prologue: fill 3 of 4 stages
    issue(0, kbeg);
    if (nk > 1) issue(1, kbeg + BK);
    if (nk > 2) issue(2, kbeg + 2 * BK);

    // per-lane invariant smem offsets (bytes)
    const uint32_t a_off = (uint32_t)((wm + (lane & 15)) * (ASTRIDE * 2) + ((lane >> 4) * 8) * 2);
    const uint32_t b_off = (uint32_t)((wn + ((lane >> 4) & 1) * 8 + (lane & 7)) * (ASTRIDE * 2)
                                      + (((lane >> 3) & 1) * 8) * 2);

    for (int i = 0; i < nk; i++) {
        // stage i must be resident; allow min(2, nk-1-i) groups still in flight
        if (i + 3 <= nk)      cp_wait2();
        else if (i + 2 <= nk) cp_wait1();
        else                  cp_wait0();
        __syncthreads();
        if (i + 3 < nk) issue((i + 3) & 3, kbeg + (i + 3) * BK);

        const uint32_t aT = sbase + (i & 3) * STAGE_BYTES;
        const uint32_t bT = aT + A_BYTES;

        #pragma unroll
        for (int ks = 0; ks < 4; ks++) {
            const uint32_t kb = ks * 32;   // 16 halves = 32 bytes
            uint32_t a[4][4], bb[2][4];
            #pragma unroll
            for (int mi = 0; mi < 4; mi++) {
                uint32_t addr = aT + a_off + mi * (16 * ASTRIDE * 2) + kb;
                asm volatile("ldmatrix.sync.aligned.m8n8.x4.shared.b16 {%0,%1,%2,%3}, [%4];\n"
                    : "=r"(a[mi][0]), "=r"(a[mi][1]), "=r"(a[mi][2]), "=r"(a[mi][3])
                    : "r"(addr));
            }
            #pragma unroll
            for (int nn = 0; nn < 2; nn++) {
                uint32_t addr = bT + b_off + nn * (16 * ASTRIDE * 2) + kb;
                asm volatile("ldmatrix.sync.aligned.m8n8.x4.shared.b16 {%0,%1,%2,%3}, [%4];\n"
                    : "=r"(bb[nn][0]), "=r"(bb[nn][1]), "=r"(bb[nn][2]), "=r"(bb[nn][3])
                    : "r"(addr));
            }
            #pragma unroll
            for (int mi = 0; mi < 4; mi++)
                #pragma unroll
                for (int ni = 0; ni < 4; ni++) {
                    asm volatile(
                        "mma.sync.aligned.m16n8k16.row.col.f32.f16.f16.f32 "
                        "{%0,%1,%2,%3}, {%4,%5,%6,%7}, {%8,%9}, {%0,%1,%2,%3};\n"
                        : "+f"(acc[mi][ni][0]), "+f"(acc[mi][ni][1]),
                          "+f"(acc[mi][ni][2]), "+f"(acc[mi][ni][3])
                        : "r"(a[mi][0]), "r"(a[mi][1]), "r"(a[mi][2]), "r"(a[mi][3]),
                          "r"(bb[ni >> 1][(ni & 1) * 2]), "r"(bb[ni >> 1][(ni & 1) * 2 + 1]));
                }
        }
    }

    const float gs = (which == 2) ? tanhf(gate[0]) : 1.0f;
    const int g8 = lane >> 2;
    const int t4 = lane & 3;
    #pragma unroll
    for (int mi = 0; mi < 4; mi++)
        #pragma unroll
        for (int ni = 0; ni < 4; ni++) {
            size_t row0 = (size_t)m_base + wm + mi * 16 + g8;
            size_t col  = (size_t)n_base + wn + ni * 8 + t4 * 2;
            C[row0 * N + col]           = acc[mi][ni][0] * gs;
            C[row0 * N + col + 1]       = acc[mi][ni][1] * gs;
            C[(row0 + 8) * N + col]     = acc[mi][ni][2] * gs;
            C[(row0 + 8) * N + col + 1] = acc[mi][ni][3] * gs;
        }
}

// ------------------------- split-K reduce (KV) --------------------------------
__global__ void reduce_kv_kernel() {
    unsigned i = blockIdx.x * 256u + threadIdx.x;
    float s = 0.f;
    #pragma unroll
    for (int p = 0; p < KV_SPLITS; p++) s += g_KVp[(size_t)p * (512u * 1024u) + i];
    g_KV[i] = s;
}

// --------------------------- attention kernel --------------------------------
// 1 block per token. g_KV row: [(b*8+ch)*32 + latent][ k: g*128+d | v: 512+g*128+d ]
// Writes y as fp16 into g_yh [2048][2048].
__global__ __launch_bounds__(256)
void attn_kernel(const int* __restrict__ mask) {
    const int tg = blockIdx.x;
    const int b  = tg >> 10;
    const int ch = mask[tg];
    const size_t kvrow0 = (size_t)((b * 8 + ch) * 32);

    __shared__ float q_s[2048];
    __shared__ float attn_s[8][32];

    {
        const float4* src = (const float4*)(g_Q + (size_t)tg * 2048);
        float4* dst = (float4*)q_s;
        for (int i = threadIdx.x; i < 512; i += 256) dst[i] = src[i];
    }
    __syncthreads();

    const int wid = threadIdx.x >> 5;
    const int lane = threadIdx.x & 31;
    const float scale = 0.08838834764831845f;   // 1/sqrt(128)

    for (int hh = 0; hh < 2; hh++) {
        const int h = wid * 2 + hh;
        const int g = h >> 2;

        const float* krow = g_KV + (kvrow0 + lane) * 1024 + g * 128;
        const float* qh = q_s + h * 128;
        float s = 0.f;
        #pragma unroll 8
        for (int d = 0; d < 128; d += 4) {
            float4 k4 = *(const float4*)(krow + d);
            s += qh[d] * k4.x + qh[d + 1] * k4.y + qh[d + 2] * k4.z + qh[d + 3] * k4.w;
        }
        s *= scale;

        float m = s;
        #pragma unroll
        for (int o = 16; o; o >>= 1) m = fmaxf(m, __shfl_xor_sync(0xffffffffu, m, o));
        float e = __expf(s - m);
        float sum = e;
        #pragma unroll
        for (int o = 16; o; o >>= 1) sum += __shfl_xor_sync(0xffffffffu, sum, o);
        attn_s[wid][lane] = e / sum;
        __syncwarp();

        float4 acc = make_float4(0.f, 0.f, 0.f, 0.f);
        const float* vbase = g_KV + kvrow0 * 1024 + 512 + g * 128 + lane * 4;
        #pragma unroll
        for (int kl = 0; kl < 32; kl++) {
            float w = attn_s[wid][kl];
            float4 v4 = *(const float4*)(vbase + (size_t)kl * 1024);
            acc.x += w * v4.x; acc.y += w * v4.y; acc.z += w * v4.z; acc.w += w * v4.w;
        }

        __half2 p0 = __floats2half2_rn(acc.x, acc.y);
        __half2 p1 = __floats2half2_rn(acc.z, acc.w);
        size_t base = (size_t)tg * 2048u + h * 128 + lane * 4;
        *(__half2*)(g_yh + base)     = p0;
        *(__half2*)(g_yh + base + 2) = p1;
        __syncwarp();
    }
}

// ------------------------------- launcher ------------------------------------
extern "C" void kernel_launch(void* const* d_in, const int* in_sizes, int n_in,
                              void* d_out, int out_size) {
    const float* x    = (const float*)d_in[0];   // (2,1024,2048)
    const float* cs   = (const float*)d_in[1];   // (2,8,32,2048)
    const int*   mask = (const int*)  d_in[2];   // (2,1024)
    const float* Wq   = (const float*)d_in[3];   // (2048,2048)
    const float* Wk   = (const float*)d_in[4];   // (2048,512)
    const float* Wv   = (const float*)d_in[5];   // (2048,512)
    const float* Wo   = (const float*)d_in[6];   // (2048,2048)
    const float* gate = (const float*)d_in[7];   // (1,)
    float* out = (float*)d_out;

    cudaFuncSetAttribute(gemm_mma_kernel,
                         cudaFuncAttributeMaxDynamicSharedMemorySize, SMEM_DYN);

    // 1) all converts in one launch
    conv_all_kernel<<<15360, 256>>>(x, cs, Wq, Wk, Wv, Wo);

    // 2) Q = x @ Wq   (2048 x 2048), 128 CTAs, K=2048
    gemm_mma_kernel<<<dim3(2048 / BN, 2048 / BM, 1), 512, SMEM_DYN>>>(0, nullptr, gate, 2048, KK / BK);

    // 3) [K|V] partials = channel_states @ [Wk|Wv]  (512 x 1024), split-K=8 -> 128 CTAs
    gemm_mma_kernel<<<dim3(1024 / BN, 512 / BM, KV_SPLITS), 512, SMEM_DYN>>>(1, nullptr, gate, 1024, KV_NK);
    reduce_kv_kernel<<<(512u * 1024u) / 256u, 256>>>();

    // 4) attention -> y (fp16)
    attn_kernel<<<2048, 256>>>(mask);

    // 5) out = (y @ Wo) * tanh(gate)   (2048 x 2048)  [profiled launch: #6]
    gemm_mma_kernel<<<dim3(2048 / BN, 2048 / BM, 1), 512, SMEM_DYN>>>(2, out, gate, 2048, KK / BK);
}